// round 9
// baseline (speedup 1.0000x reference)
#include <cuda_runtime.h>
#include <math.h>

#define NPATH 15

// Path metadata (reference enumeration order)
__constant__ int K_L1[NPATH] = {0,0,0,1,1,1,1,1,1,2,2,2,2,2,2};
__constant__ int K_L2[NPATH] = {0,1,2,0,1,1,1,2,2,0,1,1,2,2,2};
__constant__ int K_LO[NPATH] = {0,1,2,1,0,1,2,1,2,2,1,2,0,1,2};
__constant__ int K_I1[NPATH] = {0,0,0,16,16,16,16,16,16,64,64,64,64,64,64};
__constant__ int K_I2[NPATH] = {0,1,4,0,1,1,1,4,4,0,1,1,4,4,4};
__constant__ int K_COFF[NPATH]  = {0,1,10,35,44,53,80,125,170,245,270,315,390,415,490};
__constant__ int K_CCOFF[NPATH] = {0,1,4,9,18,21,30,45,54,69,94,109,134,139,154};
__constant__ int K_TMPOFF[NPATH]= {0,16,64,144,192,208,256,336,384,464,544,592,672,688,736};
// Signs decoded via the R1/R2 rel_err probes.
__constant__ float K_SIGN[NPATH] = {1,1,1,1,1, -1.f, 1,1, -1.f, 1,1, 1.f, 1, 1.f, -1.f};
// Partials: group0 (lo=0) base 0 (48), group1 (lo=1) base 48 (288),
//           group2 (lo=2) base 336 (480). Total 816.
__constant__ int K_PBASE[NPATH] = {0,48,336,48,0,48,336,48,336,336,48,336,0,48,336};
__constant__ int K_PSLOT[NPATH] = {0,0,0,1,1,2,1,3,2,3,4,4,2,5,5};
// Shape-convergent half-warp map (16 slots, -1 = idle half-warp).
// Warps 0-3 pair identical (l1,lo) codes -> both halves take the SAME branch
// (no serialization). Heaviest path p14 gets a solo warp.
__constant__ int K_PMAP[16] = {9,11, 10,13, 6,8, 3,5, 14,-1, 2,0, 7,4, 12,1};

__device__ float g_C[615];   // pre-scaled (norm, sign, sqrt(2lo+1), INV_NORM)

// ---------------------------------------------------------------------------
// Init: real-basis Wigner-3j (fp32); phase 1 one thread per entry, phase 2
// one warp per path (shuffle reductions for norm / max / sign-index).
// ---------------------------------------------------------------------------
__constant__ float FKF[9]  = {1.f,1.f,2.f,6.f,24.f,120.f,720.f,5040.f,40320.f};
__constant__ float FKFI[9] = {1.f,1.f,0.5f,1.f/6.f,1.f/24.f,1.f/120.f,1.f/720.f,
                              1.f/5040.f,1.f/40320.f};

__device__ float cg_coef_f(int l1,int m1,int l2,int m2,int L,int M){
  if (m1+m2 != M) return 0.f;
  if (abs(m1)>l1 || abs(m2)>l2 || abs(M)>L) return 0.f;
  float pref = (2.f*L+1.f)*FKF[l1+l2-L]*FKF[l1-l2+L]*FKF[-l1+l2+L]*FKFI[l1+l2+L+1];
  pref *= FKF[L+M]*FKF[L-M]*FKF[l1-m1]*FKF[l1+m1]*FKF[l2-m2]*FKF[l2+m2];
  pref = sqrtf(pref);
  float s = 0.f;
  for (int k=0;k<=l1+l2-L;k++){
    int a=l1+l2-L-k, b=l1-m1-k, c=l2+m2-k, d=L-l2+m1+k, e=L-l1-m2+k;
    if (b<0 || c<0 || d<0 || e<0) continue;
    float term = FKFI[k]*FKFI[a]*FKFI[b]*FKFI[c]*FKFI[d]*FKFI[e];
    s += (k&1) ? -term : term;
  }
  return pref*s;
}

__device__ int urow_f(int l, int r, int* ms, float* ure, float* uim){
  const float s = 0.70710678f;
  int mp = r - l;
  if (mp == 0){ ms[0]=0; ure[0]=1.f; uim[0]=0.f; return 1; }
  if (mp > 0){
    ms[0] = -mp; ure[0] = s;              uim[0] = 0.f;
    ms[1] =  mp; ure[1] = (mp&1)? -s : s; uim[1] = 0.f;
    return 2;
  }
  int am = -mp;
  ms[0] = -am; ure[0]=0.f; uim[0] = s;
  ms[1] =  am; ure[1]=0.f; uim[1] = (am&1) ? s : -s;
  return 2;
}

__global__ void wigner_init_kernel(){
  __shared__ float sre[615];
  __shared__ float sim[615];
  int t = threadIdx.x;
  if (t < 615) {
    int p = 0;
    #pragma unroll
    for (int q=1;q<NPATH;q++) if (t >= K_COFF[q]) p = q;
    int e = t - K_COFF[p];
    int l1=K_L1[p], l2=K_L2[p], lo=K_LO[p];
    int d1=2*l1+1, d2=2*l2+1;
    int k = e/(d1*d2); int rem = e - k*d1*d2;
    int i = rem/d2;    int j = rem - i*d2;

    int m3s[2]; float r3[2], i3[2];
    int n3 = urow_f(lo, k, m3s, r3, i3);
    int m1s[2]; float r1[2], i1v[2];
    int n1 = urow_f(l1, i, m1s, r1, i1v);
    int m2s[2]; float r2[2], i2v[2];
    int n2 = urow_f(l2, j, m2s, r2, i2v);
    float re=0.f, im=0.f;
    for (int a=0;a<n3;a++) for (int b=0;b<n1;b++) for (int c=0;c<n2;c++){
      int m3=m3s[a], m1=m1s[b], m2=m2s[c];
      if (m1+m2+m3 != 0) continue;
      float vc = cg_coef_f(l1,m1,l2,m2,lo,-m3);
      if (m3 & 1) vc = -vc;
      float ar=r3[a], ai=i3[a];
      float br=r1[b], bi=i1v[b];
      float cr=r2[c], ci=i2v[c];
      float xr = ar*br - ai*bi, xi = ar*bi + ai*br;
      float yr = xr*cr - xi*ci, yi = xr*ci + xi*cr;
      re += yr*vc; im += yi*vc;
    }
    sre[t] = re; sim[t] = im;
  }
  __syncthreads();
  int w = t >> 5, lane = t & 31;
  if (w < NPATH) {
    int p = w;
    int d1=2*K_L1[p]+1, d2=2*K_L2[p]+1, d3=2*K_LO[p]+1;
    int base = K_COFF[p], n = d1*d2*d3;
    float s2r=0.f, s2i=0.f;
    for (int e=lane; e<n; e+=32){
      s2r += sre[base+e]*sre[base+e];
      s2i += sim[base+e]*sim[base+e];
    }
    #pragma unroll
    for (int o=16;o;o>>=1){
      s2r += __shfl_xor_sync(0xffffffffu, s2r, o);
      s2i += __shfl_xor_sync(0xffffffffu, s2i, o);
    }
    bool useRe = (s2r >= s2i);
    float nrm = sqrtf(useRe ? s2r : s2i);
    float mx = 0.f;
    for (int e=lane; e<n; e+=32){
      float v = fabsf(useRe ? sre[base+e] : sim[base+e]);
      mx = fmaxf(mx, v);
    }
    #pragma unroll
    for (int o=16;o;o>>=1) mx = fmaxf(mx, __shfl_xor_sync(0xffffffffu, mx, o));
    int idx = 1<<30;
    for (int e=lane; e<n; e+=32){
      float v = fabsf(useRe ? sre[base+e] : sim[base+e]);
      if (v >= mx*(1.f - 1e-5f) && e < idx) idx = e;
    }
    #pragma unroll
    for (int o=16;o;o>>=1) idx = min(idx, __shfl_xor_sync(0xffffffffu, idx, o));
    float v0 = useRe ? sre[base+idx] : sim[base+idx];
    float inv = (K_LO[p]==0) ? 0.14433756729740646f : 0.10206207261596577f;
    float scale = ((v0 >= 0.f) ? 1.f : -1.f) * K_SIGN[p] * sqrtf((float)d3) / nrm * inv;
    for (int e=lane; e<n; e+=32){
      float v = useRe ? sre[base+e] : sim[base+e];
      g_C[base+e] = v*scale;
    }
  }
}

// ---------------------------------------------------------------------------
// Fused per-path body: cc -> tmp -> epilogue, templated on shape code.
// Half-warp-local syncs; epilogue uses packed fma.rn.f32x2 (FFMA2).
// ---------------------------------------------------------------------------
template<int CODE>
__device__ __forceinline__ void path_body(
    int p, int r, unsigned mask,
    const float* __restrict__ x1s, const float* __restrict__ x2s,
    float* __restrict__ ccs, float* __restrict__ tmps,
    float* __restrict__ parts, const unsigned long long (&w8)[8])
{
  constexpr int L1v = CODE/3, LOv = CODE%3;
  constexpr int D1 = 2*L1v+1, D3 = 2*LOv+1, NE = D1*D3;
  const int co = K_COFF[p], cco = K_CCOFF[p];
  const int d2 = 2*K_L2[p]+1, i2o = K_I2[p];

  // cc[e] = sum_j C[e,j] * x2[j]
  if (r < NE) {
    const float* cp = g_C + co + r*d2;
    float s = 0.f;
    for (int j=0;j<d2;j++) s = fmaf(cp[j], x2s[i2o+j], s);
    ccs[cco + r] = s;
  }
  if constexpr (NE > 16) {
    if (r < NE-16) {
      const float* cp = g_C + co + (r+16)*d2;
      float s = 0.f;
      for (int j=0;j<d2;j++) s = fmaf(cp[j], x2s[i2o+j], s);
      ccs[cco + r + 16] = s;
    }
  }
  __syncwarp(mask);

  // tmp[k][u=r] = sum_i x1[u,i] * cc[k,i]
  {
    const float* ccb = ccs + cco;
    const float* x1u = x1s + K_I1[p] + r*D1;
    float xv[D1];
    #pragma unroll
    for (int i=0;i<D1;i++) xv[i] = x1u[i];
    float* tmpb = tmps + K_TMPOFF[p] + r;
    #pragma unroll
    for (int k=0;k<D3;k++){
      float s = xv[0]*ccb[k*D1];
      #pragma unroll
      for (int i=1;i<D1;i++) s = fmaf(xv[i], ccb[k*D1+i], s);
      tmpb[k*16] = s;
    }
  }
  __syncwarp(mask);

  // partial[w=r][k] = sum_u w[u]*tmp[k][u] via packed f32x2
  {
    constexpr int NP = (D3==1) ? 3 : 6;
    const int base = K_PBASE[p] + (r*D3)*NP + K_PSLOT[p];
    const ulonglong2* tp2 = reinterpret_cast<const ulonglong2*>(tmps + K_TMPOFF[p]);
    #pragma unroll
    for (int k=0;k<D3;k++){
      ulonglong2 t0 = tp2[k*4+0], t1 = tp2[k*4+1];
      unsigned long long acc;
      asm("mul.rn.f32x2 %0, %1, %2;"     : "=l"(acc) : "l"(w8[0]), "l"(t0.x));
      asm("fma.rn.f32x2 %0, %1, %2, %0;" : "+l"(acc) : "l"(w8[1]), "l"(t0.y));
      asm("fma.rn.f32x2 %0, %1, %2, %0;" : "+l"(acc) : "l"(w8[2]), "l"(t1.x));
      asm("fma.rn.f32x2 %0, %1, %2, %0;" : "+l"(acc) : "l"(w8[3]), "l"(t1.y));
      ulonglong2 t2 = tp2[k*4+2], t3 = tp2[k*4+3];
      asm("fma.rn.f32x2 %0, %1, %2, %0;" : "+l"(acc) : "l"(w8[4]), "l"(t2.x));
      asm("fma.rn.f32x2 %0, %1, %2, %0;" : "+l"(acc) : "l"(w8[5]), "l"(t2.y));
      asm("fma.rn.f32x2 %0, %1, %2, %0;" : "+l"(acc) : "l"(w8[6]), "l"(t3.x));
      asm("fma.rn.f32x2 %0, %1, %2, %0;" : "+l"(acc) : "l"(w8[7]), "l"(t3.y));
      float lo, hi;
      asm("mov.b64 {%0,%1}, %2;" : "=f"(lo), "=f"(hi) : "l"(acc));
      parts[base + k*NP] = lo + hi;
    }
  }
}

// ---------------------------------------------------------------------------
// Main kernel: one block per batch row, 256 threads, 15 half-warp groups.
// ---------------------------------------------------------------------------
__global__ void __launch_bounds__(256, 6) tp_kernel(
    const float* __restrict__ x1, const float* __restrict__ x2,
    const float* __restrict__ wts, float* __restrict__ out)
{
  __shared__ float x1s[144];
  __shared__ float x2s[12];
  __shared__ float ccs[179];
  __shared__ __align__(16) float tmps[816];
  __shared__ float parts[816];
  const int t = threadIdx.x;
  const long long z = blockIdx.x;
  const int g = t >> 4, r = t & 15;
  const int p = K_PMAP[g];
  const unsigned mask = 0xFFFFu << (t & 16);

  // Weights: 64B/thread coalesced LDG.128, directly as packed f32x2 pairs.
  unsigned long long w8[8];
  if (p >= 0) {
    const ulonglong2* wp = reinterpret_cast<const ulonglong2*>(
        wts + z*3840 + p*256 + r*16);
    ulonglong2 a = wp[0], b = wp[1], c = wp[2], d = wp[3];
    w8[0]=a.x; w8[1]=a.y; w8[2]=b.x; w8[3]=b.y;
    w8[4]=c.x; w8[5]=c.y; w8[6]=d.x; w8[7]=d.y;
  }
  if (t < 144) x1s[t] = x1[z*144 + t];
  if (t < 9)   x2s[t] = x2[z*9 + t];
  __syncthreads();

  if (p >= 0) {
    switch (K_L1[p]*3 + K_LO[p]) {
      case 0: path_body<0>(p,r,mask,x1s,x2s,ccs,tmps,parts,w8); break;
      case 1: path_body<1>(p,r,mask,x1s,x2s,ccs,tmps,parts,w8); break;
      case 2: path_body<2>(p,r,mask,x1s,x2s,ccs,tmps,parts,w8); break;
      case 3: path_body<3>(p,r,mask,x1s,x2s,ccs,tmps,parts,w8); break;
      case 4: path_body<4>(p,r,mask,x1s,x2s,ccs,tmps,parts,w8); break;
      case 5: path_body<5>(p,r,mask,x1s,x2s,ccs,tmps,parts,w8); break;
      case 6: path_body<6>(p,r,mask,x1s,x2s,ccs,tmps,parts,w8); break;
      case 7: path_body<7>(p,r,mask,x1s,x2s,ccs,tmps,parts,w8); break;
      default: path_body<8>(p,r,mask,x1s,x2s,ccs,tmps,parts,w8); break;
    }
  }
  __syncthreads();

  if (t < 144) {
    int idx, np;
    if (t < 16)      { idx = t*3;            np = 3; }
    else if (t < 64) { idx = 48 + (t-16)*6;  np = 6; }
    else             { idx = 336 + (t-64)*6; np = 6; }
    float acc = 0.f;
    for (int s2=0; s2<np; s2++) acc += parts[idx + s2];
    out[z*144 + t] = acc;
  }
}

extern "C" void kernel_launch(void* const* d_in, const int* in_sizes, int n_in,
                              void* d_out, int out_size)
{
  const float* x1  = (const float*)d_in[0];   // features_1 [B,144]
  const float* x2  = (const float*)d_in[1];   // features_2 [B,9]
  const float* wts = (const float*)d_in[2];   // weights    [B,3840]
  float* out = (float*)d_out;                 // [B,144]
  int B = in_sizes[0] / 144;

  wigner_init_kernel<<<1, 1024>>>();
  tp_kernel<<<B, 256>>>(x1, x2, wts, out);
}

// round 10
// speedup vs baseline: 1.2313x; 1.2313x over previous
#include <cuda_runtime.h>
#include <math.h>

#define NPATH 15

// Path metadata (reference enumeration order)
__constant__ int K_L1[NPATH] = {0,0,0,1,1,1,1,1,1,2,2,2,2,2,2};
__constant__ int K_L2[NPATH] = {0,1,2,0,1,1,1,2,2,0,1,1,2,2,2};
__constant__ int K_LO[NPATH] = {0,1,2,1,0,1,2,1,2,2,1,2,0,1,2};
__constant__ int K_I1[NPATH] = {0,0,0,16,16,16,16,16,16,64,64,64,64,64,64};
__constant__ int K_I2[NPATH] = {0,1,4,0,1,1,1,4,4,0,1,1,4,4,4};
__constant__ int K_COFF[NPATH]  = {0,1,10,35,44,53,80,125,170,245,270,315,390,415,490};
__constant__ int K_CCOFF[NPATH] = {0,1,4,9,18,21,30,45,54,69,94,109,134,139,154};
__constant__ int K_TMPOFF[NPATH]= {0,16,64,144,192,208,256,336,384,464,544,592,672,688,736};
// Signs decoded via the R1/R2 rel_err probes.
__constant__ float K_SIGN[NPATH] = {1,1,1,1,1, -1.f, 1,1, -1.f, 1,1, 1.f, 1, 1.f, -1.f};
// Partials: group0 (lo=0) base 0 (48), group1 (lo=1) base 48 (288),
//           group2 (lo=2) base 336 (480). Total 816.
__constant__ int K_PBASE[NPATH] = {0,48,336,48,0,48,336,48,336,336,48,336,0,48,336};
__constant__ int K_PSLOT[NPATH] = {0,0,0,1,1,2,1,3,2,3,4,4,2,5,5};
// Shape-convergent half-warp map (16 slots, -1 = idle half).
// Warps 0-3 pair identical (l1,lo) codes: (p9,p11)=code8, (p6,p8)=code5,
// (p10,p13)=code7, (p4,p5)=code4 -> both halves take the SAME branch.
// Leftovers minimize serial cost: (14,-1)=5, (2,0)=6, (7,1)=6, (3,12)=2.
__constant__ int K_PMAP[16] = {9,11, 6,8, 10,13, 4,5, 14,-1, 2,0, 7,1, 3,12};

__device__ float g_C[615];   // pre-scaled (norm, sign, sqrt(2lo+1), INV_NORM)

// ---------------------------------------------------------------------------
// Init: real-basis Wigner-3j (fp32); phase 1 one thread per entry, phase 2
// one warp per path (shuffle reductions).
// ---------------------------------------------------------------------------
__constant__ float FKF[9]  = {1.f,1.f,2.f,6.f,24.f,120.f,720.f,5040.f,40320.f};
__constant__ float FKFI[9] = {1.f,1.f,0.5f,1.f/6.f,1.f/24.f,1.f/120.f,1.f/720.f,
                              1.f/5040.f,1.f/40320.f};

__device__ float cg_coef_f(int l1,int m1,int l2,int m2,int L,int M){
  if (m1+m2 != M) return 0.f;
  if (abs(m1)>l1 || abs(m2)>l2 || abs(M)>L) return 0.f;
  float pref = (2.f*L+1.f)*FKF[l1+l2-L]*FKF[l1-l2+L]*FKF[-l1+l2+L]*FKFI[l1+l2+L+1];
  pref *= FKF[L+M]*FKF[L-M]*FKF[l1-m1]*FKF[l1+m1]*FKF[l2-m2]*FKF[l2+m2];
  pref = sqrtf(pref);
  float s = 0.f;
  for (int k=0;k<=l1+l2-L;k++){
    int a=l1+l2-L-k, b=l1-m1-k, c=l2+m2-k, d=L-l2+m1+k, e=L-l1-m2+k;
    if (b<0 || c<0 || d<0 || e<0) continue;
    float term = FKFI[k]*FKFI[a]*FKFI[b]*FKFI[c]*FKFI[d]*FKFI[e];
    s += (k&1) ? -term : term;
  }
  return pref*s;
}

__device__ int urow_f(int l, int r, int* ms, float* ure, float* uim){
  const float s = 0.70710678f;
  int mp = r - l;
  if (mp == 0){ ms[0]=0; ure[0]=1.f; uim[0]=0.f; return 1; }
  if (mp > 0){
    ms[0] = -mp; ure[0] = s;              uim[0] = 0.f;
    ms[1] =  mp; ure[1] = (mp&1)? -s : s; uim[1] = 0.f;
    return 2;
  }
  int am = -mp;
  ms[0] = -am; ure[0]=0.f; uim[0] = s;
  ms[1] =  am; ure[1]=0.f; uim[1] = (am&1) ? s : -s;
  return 2;
}

__global__ void wigner_init_kernel(){
  __shared__ float sre[615];
  __shared__ float sim[615];
  int t = threadIdx.x;
  if (t < 615) {
    int p = 0;
    #pragma unroll
    for (int q=1;q<NPATH;q++) if (t >= K_COFF[q]) p = q;
    int e = t - K_COFF[p];
    int l1=K_L1[p], l2=K_L2[p], lo=K_LO[p];
    int d1=2*l1+1, d2=2*l2+1;
    int k = e/(d1*d2); int rem = e - k*d1*d2;
    int i = rem/d2;    int j = rem - i*d2;

    int m3s[2]; float r3[2], i3[2];
    int n3 = urow_f(lo, k, m3s, r3, i3);
    int m1s[2]; float r1[2], i1v[2];
    int n1 = urow_f(l1, i, m1s, r1, i1v);
    int m2s[2]; float r2[2], i2v[2];
    int n2 = urow_f(l2, j, m2s, r2, i2v);
    float re=0.f, im=0.f;
    for (int a=0;a<n3;a++) for (int b=0;b<n1;b++) for (int c=0;c<n2;c++){
      int m3=m3s[a], m1=m1s[b], m2=m2s[c];
      if (m1+m2+m3 != 0) continue;
      float vc = cg_coef_f(l1,m1,l2,m2,lo,-m3);
      if (m3 & 1) vc = -vc;
      float ar=r3[a], ai=i3[a];
      float br=r1[b], bi=i1v[b];
      float cr=r2[c], ci=i2v[c];
      float xr = ar*br - ai*bi, xi = ar*bi + ai*br;
      float yr = xr*cr - xi*ci, yi = xr*ci + xi*cr;
      re += yr*vc; im += yi*vc;
    }
    sre[t] = re; sim[t] = im;
  }
  __syncthreads();
  int w = t >> 5, lane = t & 31;
  if (w < NPATH) {
    int p = w;
    int d1=2*K_L1[p]+1, d2=2*K_L2[p]+1, d3=2*K_LO[p]+1;
    int base = K_COFF[p], n = d1*d2*d3;
    float s2r=0.f, s2i=0.f;
    for (int e=lane; e<n; e+=32){
      s2r += sre[base+e]*sre[base+e];
      s2i += sim[base+e]*sim[base+e];
    }
    #pragma unroll
    for (int o=16;o;o>>=1){
      s2r += __shfl_xor_sync(0xffffffffu, s2r, o);
      s2i += __shfl_xor_sync(0xffffffffu, s2i, o);
    }
    bool useRe = (s2r >= s2i);
    float nrm = sqrtf(useRe ? s2r : s2i);
    float mx = 0.f;
    for (int e=lane; e<n; e+=32){
      float v = fabsf(useRe ? sre[base+e] : sim[base+e]);
      mx = fmaxf(mx, v);
    }
    #pragma unroll
    for (int o=16;o;o>>=1) mx = fmaxf(mx, __shfl_xor_sync(0xffffffffu, mx, o));
    int idx = 1<<30;
    for (int e=lane; e<n; e+=32){
      float v = fabsf(useRe ? sre[base+e] : sim[base+e]);
      if (v >= mx*(1.f - 1e-5f) && e < idx) idx = e;
    }
    #pragma unroll
    for (int o=16;o;o>>=1) idx = min(idx, __shfl_xor_sync(0xffffffffu, idx, o));
    float v0 = useRe ? sre[base+idx] : sim[base+idx];
    float inv = (K_LO[p]==0) ? 0.14433756729740646f : 0.10206207261596577f;
    float scale = ((v0 >= 0.f) ? 1.f : -1.f) * K_SIGN[p] * sqrtf((float)d3) / nrm * inv;
    for (int e=lane; e<n; e+=32){
      float v = useRe ? sre[base+e] : sim[base+e];
      g_C[base+e] = v*scale;
    }
  }
}

// ---------------------------------------------------------------------------
// Templated inner phases (fully unrolled, scalar LDS -> low reg pressure)
// ---------------------------------------------------------------------------
template<int D1, int D3>
__device__ __forceinline__ void tmp_phase(const float* __restrict__ x1u,
                                          const float* __restrict__ ccb,
                                          float* __restrict__ tmpb){
  #pragma unroll
  for (int k=0;k<D3;k++){
    float s = x1u[0]*ccb[k*D1];
    #pragma unroll
    for (int i=1;i<D1;i++) s = fmaf(x1u[i], ccb[k*D1+i], s);
    tmpb[k*16] = s;
  }
}

template<int D3>
__device__ __forceinline__ void epi_phase(const float (&wr)[16],
                                          const float4* __restrict__ tmps4,
                                          int tmo4, float* __restrict__ parts,
                                          int pidx){
  const int NP = (D3==1) ? 3 : 6;
  #pragma unroll
  for (int k=0;k<D3;k++){
    float4 a = tmps4[tmo4 + k*4 + 0];
    float4 b = tmps4[tmo4 + k*4 + 1];
    float s = wr[0]*a.x;
    s = fmaf(wr[1],  a.y, s); s = fmaf(wr[2],  a.z, s); s = fmaf(wr[3],  a.w, s);
    s = fmaf(wr[4],  b.x, s); s = fmaf(wr[5],  b.y, s);
    s = fmaf(wr[6],  b.z, s); s = fmaf(wr[7],  b.w, s);
    float4 c = tmps4[tmo4 + k*4 + 2];
    float4 d = tmps4[tmo4 + k*4 + 3];
    s = fmaf(wr[8],  c.x, s); s = fmaf(wr[9],  c.y, s);
    s = fmaf(wr[10], c.z, s); s = fmaf(wr[11], c.w, s);
    s = fmaf(wr[12], d.x, s); s = fmaf(wr[13], d.y, s);
    s = fmaf(wr[14], d.z, s); s = fmaf(wr[15], d.w, s);
    parts[pidx + k*NP] = s;
  }
}

// ---------------------------------------------------------------------------
// Main kernel: one block per batch row, 256 threads, 15 half-warp path groups.
// ---------------------------------------------------------------------------
__global__ void __launch_bounds__(256, 6) tp_kernel(
    const float* __restrict__ x1, const float* __restrict__ x2,
    const float* __restrict__ wts, float* __restrict__ out)
{
  __shared__ float x1s[144];
  __shared__ float x2s[12];
  __shared__ float ccs[179];                  // cc[k*d1+i] per path
  __shared__ __align__(16) float tmps[816];   // per path: tmo + k*16 + u
  __shared__ float parts[816];
  const int t = threadIdx.x;
  const long long z = blockIdx.x;

  const int g = t >> 4, r = t & 15;
  const int p = K_PMAP[g];

  // Prefetch this thread's 16 contiguous weights (64B/thread, coalesced).
  float wr[16];
  if (p >= 0) {
    const float4* wp = reinterpret_cast<const float4*>(wts + z*3840 + p*256 + r*16);
    float4 v0 = wp[0], v1 = wp[1], v2 = wp[2], v3 = wp[3];
    wr[0]=v0.x;  wr[1]=v0.y;  wr[2]=v0.z;  wr[3]=v0.w;
    wr[4]=v1.x;  wr[5]=v1.y;  wr[6]=v1.z;  wr[7]=v1.w;
    wr[8]=v2.x;  wr[9]=v2.y;  wr[10]=v2.z; wr[11]=v2.w;
    wr[12]=v3.x; wr[13]=v3.y; wr[14]=v3.z; wr[15]=v3.w;
  }
  if (t < 144) x1s[t] = x1[z*144 + t];
  if (t < 9)   x2s[t] = x2[z*9 + t];
  __syncthreads();

  const int code = (p >= 0) ? (K_L1[p]*3 + K_LO[p]) : -1;

  // cc[k,i] = sum_j C[k,i,j] * x2[j]   (lanes stride-16 over d3*d1 entries)
  if (p >= 0) {
    int d1 = 2*K_L1[p]+1, d2 = 2*K_L2[p]+1, d3 = 2*K_LO[p]+1;
    int co = K_COFF[p], cco = K_CCOFF[p], i2o = K_I2[p];
    int nE = d3*d1;
    for (int e = r; e < nE; e += 16) {
      const float* cp = g_C + co + e*d2;
      float s = 0.f;
      for (int j=0;j<d2;j++) s = fmaf(cp[j], x2s[i2o+j], s);
      ccs[cco + e] = s;
    }
  }
  __syncwarp();   // cc -> tmp is warp-internal (path groups are half-warps)

  // tmp[k][u] = sum_i x1[u,i] * cc[k,i]
  if (p >= 0) {
    const float* ccb = ccs + K_CCOFF[p];
    float* tmpb = tmps + K_TMPOFF[p] + r;
    const float* x1b = x1s + K_I1[p];
    switch (code) {
      case 0: tmp_phase<1,1>(x1b + r,   ccb, tmpb); break;  // l1=0 lo=0
      case 1: tmp_phase<1,3>(x1b + r,   ccb, tmpb); break;  // l1=0 lo=1
      case 2: tmp_phase<1,5>(x1b + r,   ccb, tmpb); break;  // l1=0 lo=2
      case 3: tmp_phase<3,1>(x1b + r*3, ccb, tmpb); break;  // l1=1 lo=0
      case 4: tmp_phase<3,3>(x1b + r*3, ccb, tmpb); break;  // l1=1 lo=1
      case 5: tmp_phase<3,5>(x1b + r*3, ccb, tmpb); break;  // l1=1 lo=2
      case 6: tmp_phase<5,1>(x1b + r*5, ccb, tmpb); break;  // l1=2 lo=0
      case 7: tmp_phase<5,3>(x1b + r*5, ccb, tmpb); break;  // l1=2 lo=1
      default: tmp_phase<5,5>(x1b + r*5, ccb, tmpb); break; // l1=2 lo=2
    }
  }
  __syncwarp();   // tmp -> epilogue is warp-internal

  // partial[w=r][k] = sum_u wr[u] * tmp[k][u] -> distinct smem slot
  if (p >= 0) {
    const float4* tmps4 = reinterpret_cast<const float4*>(tmps);
    int tmo4 = K_TMPOFF[p] >> 2;
    int lo = K_LO[p];
    int slot = K_PSLOT[p];
    if (lo == 0)      epi_phase<1>(wr, tmps4, tmo4, parts, K_PBASE[p] + r*3  + slot);
    else if (lo == 1) epi_phase<3>(wr, tmps4, tmo4, parts, K_PBASE[p] + (r*3)*6 + slot);
    else              epi_phase<5>(wr, tmps4, tmo4, parts, K_PBASE[p] + (r*5)*6 + slot);
  }
  __syncthreads();

  if (t < 144) {
    int idx, np;
    if (t < 16)      { idx = t*3;            np = 3; }
    else if (t < 64) { idx = 48 + (t-16)*6;  np = 6; }
    else             { idx = 336 + (t-64)*6; np = 6; }
    float acc = 0.f;
    for (int s2=0; s2<np; s2++) acc += parts[idx + s2];
    out[z*144 + t] = acc;
  }
}

extern "C" void kernel_launch(void* const* d_in, const int* in_sizes, int n_in,
                              void* d_out, int out_size)
{
  const float* x1  = (const float*)d_in[0];   // features_1 [B,144]
  const float* x2  = (const float*)d_in[1];   // features_2 [B,9]
  const float* wts = (const float*)d_in[2];   // weights    [B,3840]
  float* out = (float*)d_out;                 // [B,144]
  int B = in_sizes[0] / 144;

  wigner_init_kernel<<<1, 1024>>>();
  tp_kernel<<<B, 256>>>(x1, x2, wts, out);
}